// round 1
// baseline (speedup 1.0000x reference)
#include <cuda_runtime.h>

// SNNLayer: per-cell (1x32) @ (32x32) matvec, then sum of 4 more (32x32)
// matvecs, scaled by 0.8. Pure streaming / HBM-bound: 1.35 GB read per call.
//
// Layouts (row-major, per metadata order):
//   d_in[0] x              : (256,256,1,32)      -> 65536 * 32 floats
//   d_in[1] input_matrix   : (256,256,32,32)     -> 65536 * 1024 floats
//   d_in[2] layer_weights  : (4,256,256,32,32)   -> 4 * 65536 * 1024 floats
//   d_out                  : (256,256,1,32)      -> 65536 * 32 floats
//
// One warp per cell. Lane l owns output/column index l, so every inner-loop
// global load is a coalesced 128B transaction. x and the intermediate
// "active" vector are staged in shared memory (broadcast reads, no bank
// conflicts) to keep SHFL off the critical path.

#define NCELLS   65536
#define NDIM     32
#define MAT_ELEMS 1024          // 32*32
#define WARPS_PER_BLOCK 8
#define THREADS  (WARPS_PER_BLOCK * 32)
#define DECAY    0.8f

__global__ __launch_bounds__(THREADS)
void snn_layer_kernel(const float* __restrict__ x,
                      const float* __restrict__ input_matrix,
                      const float* __restrict__ layer_weights,
                      float* __restrict__ out)
{
    const int lane  = threadIdx.x & 31;
    const int wloc  = threadIdx.x >> 5;
    const int cell  = blockIdx.x * WARPS_PER_BLOCK + wloc;
    if (cell >= NCELLS) return;

    __shared__ float s_x[WARPS_PER_BLOCK][NDIM];
    __shared__ float s_act[WARPS_PER_BLOCK][NDIM];

    // Stage x for this cell (one coalesced 128B load per warp).
    s_x[wloc][lane] = x[(size_t)cell * NDIM + lane];
    __syncwarp();

    // active[lane] = sum_k x[k] * M[k][lane]   (column-l loads: coalesced)
    const float* __restrict__ Mc = input_matrix + (size_t)cell * MAT_ELEMS;
    float act = 0.0f;
#pragma unroll
    for (int k = 0; k < NDIM; ++k) {
        act = fmaf(s_x[wloc][k], Mc[k * NDIM + lane], act);
    }
    s_act[wloc][lane] = act;
    __syncwarp();

    // acc[lane] = sum_d sum_n active[n] * W_d[n][lane]
    float acc = 0.0f;
    const float* __restrict__ Wc = layer_weights + (size_t)cell * MAT_ELEMS;
#pragma unroll
    for (int d = 0; d < 4; ++d) {
        const float* __restrict__ Wd = Wc + (size_t)d * NCELLS * MAT_ELEMS;
#pragma unroll
        for (int n = 0; n < NDIM; ++n) {
            acc = fmaf(s_act[wloc][n], Wd[n * NDIM + lane], acc);
        }
    }

    out[(size_t)cell * NDIM + lane] = DECAY * acc;
}

extern "C" void kernel_launch(void* const* d_in, const int* in_sizes, int n_in,
                              void* d_out, int out_size)
{
    const float* x  = (const float*)d_in[0];
    const float* im = (const float*)d_in[1];
    const float* lw = (const float*)d_in[2];
    float* out      = (float*)d_out;

    const int blocks = NCELLS / WARPS_PER_BLOCK;   // 8192
    snn_layer_kernel<<<blocks, THREADS>>>(x, im, lw, out);
}

// round 2
// speedup vs baseline: 1.1064x; 1.1064x over previous
#include <cuda_runtime.h>

// SNNLayer, R2: vectorized (LDG.128) streaming version.
//
//   d_in[0] x              : (256,256,1,32)
//   d_in[1] input_matrix   : (256,256,32,32)
//   d_in[2] layer_weights  : (4,256,256,32,32)
//   out                    : (256,256,1,32)
//
// One warp per cell. Lane l = (r = l>>3, c = l&7). Each iteration the warp
// loads 4 consecutive 32-float rows as float4s (one LDG.128 / lane = 512B
// coalesced). Lane accumulates partial column sums for columns 4c..4c+3 over
// rows k with k%4 == r; partials are reduced across the 4 r-groups with
// shfl.xor(8) + shfl.xor(16). __ldcs: data is touched exactly once.

#define NCELLS   65536
#define NDIM     32
#define MAT_F4   256            // 1024 floats = 256 float4
#define WARPS_PER_BLOCK 8
#define THREADS  (WARPS_PER_BLOCK * 32)
#define DECAY    0.8f
#define FULLMASK 0xFFFFFFFFu

__device__ __forceinline__ void reduce_xor(float4& a)
{
#pragma unroll
    for (int m = 8; m <= 16; m <<= 1) {
        a.x += __shfl_xor_sync(FULLMASK, a.x, m);
        a.y += __shfl_xor_sync(FULLMASK, a.y, m);
        a.z += __shfl_xor_sync(FULLMASK, a.z, m);
        a.w += __shfl_xor_sync(FULLMASK, a.w, m);
    }
}

__global__ __launch_bounds__(THREADS)
void snn_layer_kernel(const float* __restrict__ x,
                      const float4* __restrict__ input_matrix,
                      const float4* __restrict__ layer_weights,
                      float4* __restrict__ out)
{
    const int lane = threadIdx.x & 31;
    const int wloc = threadIdx.x >> 5;
    const int r    = lane >> 3;     // row-subgroup 0..3
    const int c    = lane & 7;      // column quad 0..7
    const int cell = blockIdx.x * WARPS_PER_BLOCK + wloc;

    __shared__ float s_x[WARPS_PER_BLOCK][NDIM];
    __shared__ float s_act[WARPS_PER_BLOCK][NDIM];

    // Stage x (one coalesced 128B load per warp).
    s_x[wloc][lane] = x[(size_t)cell * NDIM + lane];
    __syncwarp();

    // ---- Stage 1: act[l] = sum_k x[k] * M[k][l] ----
    const float4* __restrict__ M4 = input_matrix + (size_t)cell * MAT_F4;
    float4 acc = make_float4(0.f, 0.f, 0.f, 0.f);
#pragma unroll
    for (int i = 0; i < 8; ++i) {
        const int k = i * 4 + r;                 // row index handled by this lane
        const float4 m = __ldcs(&M4[k * 8 + c]); // 512B coalesced per warp
        const float xv = s_x[wloc][k];
        acc.x = fmaf(xv, m.x, acc.x);
        acc.y = fmaf(xv, m.y, acc.y);
        acc.z = fmaf(xv, m.z, acc.z);
        acc.w = fmaf(xv, m.w, acc.w);
    }
    reduce_xor(acc);
    if (r == 0) ((float4*)s_act[wloc])[c] = acc;
    __syncwarp();

    // ---- Stage 2: acc2[l] = sum_d sum_n act[n] * W_d[n][l] ----
    float4 acc2 = make_float4(0.f, 0.f, 0.f, 0.f);
    const float4* __restrict__ Wc = layer_weights + (size_t)cell * MAT_F4;
#pragma unroll
    for (int d = 0; d < 4; ++d) {
        const float4* __restrict__ Wd = Wc + (size_t)d * NCELLS * MAT_F4;
#pragma unroll
        for (int i = 0; i < 8; ++i) {
            const int n = i * 4 + r;
            const float4 w = __ldcs(&Wd[n * 8 + c]);
            const float av = s_act[wloc][n];
            acc2.x = fmaf(av, w.x, acc2.x);
            acc2.y = fmaf(av, w.y, acc2.y);
            acc2.z = fmaf(av, w.z, acc2.z);
            acc2.w = fmaf(av, w.w, acc2.w);
        }
    }
    reduce_xor(acc2);

    if (r == 0) {
        acc2.x *= DECAY; acc2.y *= DECAY; acc2.z *= DECAY; acc2.w *= DECAY;
        out[(size_t)cell * 8 + c] = acc2;   // 128B coalesced per warp
    }
}

extern "C" void kernel_launch(void* const* d_in, const int* in_sizes, int n_in,
                              void* d_out, int out_size)
{
    const float*  x  = (const float*)d_in[0];
    const float4* im = (const float4*)d_in[1];
    const float4* lw = (const float4*)d_in[2];
    float4* out      = (float4*)d_out;

    const int blocks = NCELLS / WARPS_PER_BLOCK;   // 8192
    snn_layer_kernel<<<blocks, THREADS>>>(x, im, lw, out);
}

// round 3
// speedup vs baseline: 1.1308x; 1.0221x over previous
#include <cuda_runtime.h>

// SNNLayer, R3: barrier-free, smem-free streaming version.
//
//   d_in[0] x              : (256,256,1,32)
//   d_in[1] input_matrix   : (256,256,32,32)
//   d_in[2] layer_weights  : (4,256,256,32,32)
//   out                    : (256,256,1,32)
//
// One warp per cell, lane l = (r=l>>3, c=l&7). All cross-lane traffic is
// SHFL (no shared memory, no __syncwarp), so the 32 stage-2 LDG.128s are
// free to be hoisted by ptxas above the stage-1 reduction — no load-silent
// window per warp.
//
// Stage-1 reduce (xor 8,16) leaves every lane with the full quad
// act[4c..4c+3]; component r of that quad at lane (r,c) is act[4c+r].
// Stage 2 needs act[4i+r] per iteration i: that's component r of quad i,
// held (as "sel") at lane (r, c=i) -> shfl(sel, r*8+i).

#define NCELLS   65536
#define NDIM     32
#define MAT_F4   256            // 1024 floats = 256 float4
#define WARPS_PER_BLOCK 8
#define THREADS  (WARPS_PER_BLOCK * 32)
#define DECAY    0.8f
#define FULLMASK 0xFFFFFFFFu

__device__ __forceinline__ void reduce_xor(float4& a)
{
#pragma unroll
    for (int m = 8; m <= 16; m <<= 1) {
        a.x += __shfl_xor_sync(FULLMASK, a.x, m);
        a.y += __shfl_xor_sync(FULLMASK, a.y, m);
        a.z += __shfl_xor_sync(FULLMASK, a.z, m);
        a.w += __shfl_xor_sync(FULLMASK, a.w, m);
    }
}

__global__ __launch_bounds__(THREADS, 4)
void snn_layer_kernel(const float* __restrict__ x,
                      const float4* __restrict__ input_matrix,
                      const float4* __restrict__ layer_weights,
                      float4* __restrict__ out)
{
    const int lane = threadIdx.x & 31;
    const int wloc = threadIdx.x >> 5;
    const int r    = lane >> 3;     // row-subgroup 0..3
    const int c    = lane & 7;      // column quad 0..7
    const int cell = blockIdx.x * WARPS_PER_BLOCK + wloc;

    // Lane l holds x[l] for this cell (coalesced 128B per warp).
    const float xreg = x[(size_t)cell * NDIM + lane];

    // ---- Stage 1: act[l] = sum_k x[k] * M[k][l] ----
    const float4* __restrict__ M4 = input_matrix + (size_t)cell * MAT_F4;
    float4 acc = make_float4(0.f, 0.f, 0.f, 0.f);
#pragma unroll
    for (int i = 0; i < 8; ++i) {
        const int k = i * 4 + r;
        const float4 m = __ldcs(&M4[k * 8 + c]);      // 512B coalesced
        const float xv = __shfl_sync(FULLMASK, xreg, k);
        acc.x = fmaf(xv, m.x, acc.x);
        acc.y = fmaf(xv, m.y, acc.y);
        acc.z = fmaf(xv, m.z, acc.z);
        acc.w = fmaf(xv, m.w, acc.w);
    }
    reduce_xor(acc);

    // sel = act[4c + r]  (component r of this lane's quad)
    const float sel = (r == 0) ? acc.x : (r == 1) ? acc.y
                     : (r == 2) ? acc.z : acc.w;

    // Broadcast: av[i] = act[4i + r]  (component r of quad i, at lane r*8+i)
    float av[8];
#pragma unroll
    for (int i = 0; i < 8; ++i)
        av[i] = __shfl_sync(FULLMASK, sel, (r << 3) + i);

    // ---- Stage 2: acc2[l] = sum_d sum_n act[n] * W_d[n][l] ----
    float4 acc2 = make_float4(0.f, 0.f, 0.f, 0.f);
    const float4* __restrict__ Wc = layer_weights + (size_t)cell * MAT_F4;
#pragma unroll
    for (int d = 0; d < 4; ++d) {
        const float4* __restrict__ Wd = Wc + (size_t)d * NCELLS * MAT_F4;
#pragma unroll
        for (int i = 0; i < 8; ++i) {
            const int n = i * 4 + r;
            const float4 w = __ldcs(&Wd[n * 8 + c]);  // independent of stage 1
            acc2.x = fmaf(av[i], w.x, acc2.x);
            acc2.y = fmaf(av[i], w.y, acc2.y);
            acc2.z = fmaf(av[i], w.z, acc2.z);
            acc2.w = fmaf(av[i], w.w, acc2.w);
        }
    }
    reduce_xor(acc2);

    if (r == 0) {
        acc2.x *= DECAY; acc2.y *= DECAY; acc2.z *= DECAY; acc2.w *= DECAY;
        out[(size_t)cell * 8 + c] = acc2;             // 128B coalesced
    }
}

extern "C" void kernel_launch(void* const* d_in, const int* in_sizes, int n_in,
                              void* d_out, int out_size)
{
    const float*  x  = (const float*)d_in[0];
    const float4* im = (const float4*)d_in[1];
    const float4* lw = (const float4*)d_in[2];
    float4* out      = (float4*)d_out;

    const int blocks = NCELLS / WARPS_PER_BLOCK;   // 8192
    snn_layer_kernel<<<blocks, THREADS>>>(x, im, lw, out);
}